// round 1
// baseline (speedup 1.0000x reference)
#include <cuda_runtime.h>
#include <math.h>

#define IMG_W 8192

// ---------------- scratch (device globals; no allocation allowed) ----------------
// activation accumulators (raw conv outputs, pre-BN):
// acc0 64x128x128, acc1 64x64x64, acc2 64x32x32, acc3 64x16x16, acc4 64x8x8
__device__ float g_accs[1396736];
__device__ const int OFFS[5] = {0, 1048576, 1310720, 1376256, 1392640};

__device__ float g_im[256 * 256];   // 255 - resized
__device__ float g_xb[256 * 256];   // after dilate+invert (conv0 input)
__device__ int   g_colflag[8192];
__device__ int   g_rowflag[8192];
__device__ int   g_bounds[4];       // top, bottom, left, right
__device__ float g_scale[320];      // per-layer folded BN scale  (5 layers x 64 ch)
__device__ float g_shift[320];      // per-layer folded BN shift (incl. conv bias)

// ---------------- prep: zero atomic accumulators + fold BN params ----------------
__global__ void prep_kernel(const float* __restrict__ conv0_b,
                            const float* __restrict__ convs_b,
                            const float* __restrict__ gamma,
                            const float* __restrict__ beta,
                            const float* __restrict__ mean,
                            const float* __restrict__ var)
{
    int gid = blockIdx.x * blockDim.x + threadIdx.x;
    int stride = gridDim.x * blockDim.x;
    // zero acc1..acc4 (conv0 writes acc0 with plain stores)
    for (int k = gid; k < 348160; k += stride) g_accs[1048576 + k] = 0.0f;
    if (gid < 320) {
        int l = gid >> 6, c = gid & 63;
        float sc = gamma[gid] / sqrtf(var[gid] + 1e-5f);
        float b = (l == 0) ? conv0_b[c] : convs_b[(l - 1) * 64 + c];
        g_scale[gid] = sc;
        g_shift[gid] = (b - mean[gid]) * sc + beta[gid];
    }
}

// ---------------- crop-bound scans with data-dependent early exit ----------------
// col_var[c] = exists r: img[r][c] != img[0][c]
__global__ void col_scan_kernel(const float* __restrict__ img)
{
    int c = blockIdx.x * 256 + threadIdx.x;  // one column per thread, coalesced
    float ref = img[c];
    bool found = false;
    for (int r = 1; r < IMG_W; r++) {
        float v = img[r * IMG_W + c];
        found |= (v != ref);
        if (__all_sync(0xffffffffu, found)) break;  // warp exits once all 32 cols differ
    }
    g_colflag[c] = found ? 1 : 0;  // each column written exactly once -> no init needed
}

// row_var[r] = exists c: img[r][c] != img[r][0]
__global__ void row_scan_kernel(const float* __restrict__ img)
{
    int warp = blockIdx.x * 8 + (threadIdx.x >> 5);  // one warp per row
    int lane = threadIdx.x & 31;
    const float* rowp = img + warp * IMG_W;
    float v = rowp[lane];
    float ref = __shfl_sync(0xffffffffu, v, 0);
    int flag = __any_sync(0xffffffffu, v != ref) ? 1 : 0;
    for (int base = 32; base < IMG_W && !flag; base += 32) {
        v = rowp[base + lane];
        if (__any_sync(0xffffffffu, v != ref)) flag = 1;
    }
    if (lane == 0) g_rowflag[warp] = flag;
}

__global__ void bounds_kernel()
{
    __shared__ int smn[256], smx[256];
    int t = threadIdx.x;

    int mn = 1 << 30, mx = -1;
    for (int i = t; i < 8192; i += 256)
        if (g_colflag[i]) { if (i < mn) mn = i; if (i > mx) mx = i; }
    smn[t] = mn; smx[t] = mx;
    __syncthreads();
    for (int s = 128; s > 0; s >>= 1) {
        if (t < s) { smn[t] = min(smn[t], smn[t + s]); smx[t] = max(smx[t], smx[t + s]); }
        __syncthreads();
    }
    if (t == 0) {
        g_bounds[2] = (smx[0] >= 0) ? smn[0] : 0;
        g_bounds[3] = (smx[0] >= 0) ? smx[0] : (IMG_W - 1);
    }
    __syncthreads();

    mn = 1 << 30; mx = -1;
    for (int i = t; i < 8192; i += 256)
        if (g_rowflag[i]) { if (i < mn) mn = i; if (i > mx) mx = i; }
    smn[t] = mn; smx[t] = mx;
    __syncthreads();
    for (int s = 128; s > 0; s >>= 1) {
        if (t < s) { smn[t] = min(smn[t], smn[t + s]); smx[t] = max(smx[t], smx[t + s]); }
        __syncthreads();
    }
    if (t == 0) {
        g_bounds[0] = (smx[0] >= 0) ? smn[0] : 0;
        g_bounds[1] = (smx[0] >= 0) ? smx[0] : (IMG_W - 1);
    }
}

// ---------------- fused crop + bilinear resize + (255 - x) ----------------
__global__ void resize_kernel(const float* __restrict__ img)
{
    int y = blockIdx.x, x = threadIdx.x;  // 256 x 256
    int top = g_bounds[0], bottom = g_bounds[1], left = g_bounds[2], right = g_bounds[3];
    float szy = (float)(bottom - top + 1);
    float szx = (float)(right - left + 1);
    float cy = (float)top  + ((float)y + 0.5f) * szy * (1.0f / 256.0f) - 0.5f;
    float cx = (float)left + ((float)x + 0.5f) * szx * (1.0f / 256.0f) - 0.5f;
    float fy0 = floorf(cy), fx0 = floorf(cx);
    float wy = cy - fy0, wx = cx - fx0;
    int y0 = (int)fminf(fmaxf(fy0,        (float)top),  (float)bottom);
    int y1 = (int)fminf(fmaxf(fy0 + 1.0f, (float)top),  (float)bottom);
    int x0 = (int)fminf(fmaxf(fx0,        (float)left), (float)right);
    int x1 = (int)fminf(fmaxf(fx0 + 1.0f, (float)left), (float)right);
    float v00 = img[y0 * IMG_W + x0];
    float v01 = img[y0 * IMG_W + x1];
    float v10 = img[y1 * IMG_W + x0];
    float v11 = img[y1 * IMG_W + x1];
    float tr = v00 * (1.0f - wx) + v01 * wx;
    float br = v10 * (1.0f - wx) + v11 * wx;
    float r  = tr * (1.0f - wy) + br * wy;
    g_im[y * 256 + x] = 255.0f - r;
}

// ---------------- dilated 3x3 ones conv (rhs_dilation=2, SAME) + clip + invert ----
__global__ void dilate_kernel()
{
    int y = blockIdx.x, x = threadIdx.x;
    float s = 0.0f;
    #pragma unroll
    for (int dy = -2; dy <= 2; dy += 2) {
        int yy = y + dy;
        if ((unsigned)yy >= 256u) continue;
        #pragma unroll
        for (int dx = -2; dx <= 2; dx += 2) {
            int xx = x + dx;
            if ((unsigned)xx < 256u) s += g_im[yy * 256 + xx];
        }
    }
    float d = fminf(fmaxf(s, 0.0f), 255.0f);
    g_xb[y * 256 + x] = 255.0f - d;
}

// ---------------- conv0: 1->64 ch, 3x3, stride 2, pad 1 (raw output, no BN) ------
__global__ void conv0_kernel(const float* __restrict__ w)
{
    int tile = blockIdx.x;               // 64 tiles of 16x16 over 128x128 output
    int ty = tile >> 3, tx = tile & 7;
    int ly = threadIdx.x >> 4, lx = threadIdx.x & 15;
    int oy = ty * 16 + ly, ox = tx * 16 + lx;
    int ocb = blockIdx.y * 4;            // 16 oc groups of 4

    float v[9];
    #pragma unroll
    for (int ky = 0; ky < 3; ky++) {
        int iy = 2 * oy + ky - 1;
        #pragma unroll
        for (int kx = 0; kx < 3; kx++) {
            int ix = 2 * ox + kx - 1;
            float val = 0.0f;
            if ((unsigned)iy < 256u && (unsigned)ix < 256u) val = g_xb[iy * 256 + ix];
            v[ky * 3 + kx] = val;
        }
    }
    #pragma unroll
    for (int j = 0; j < 4; j++) {
        int oc = ocb + j;
        float acc = 0.0f;
        #pragma unroll
        for (int k = 0; k < 9; k++) acc = fmaf(v[k], __ldg(&w[oc * 9 + k]), acc);
        g_accs[(oc * 128 + oy) * 128 + ox] = acc;  // acc0 at offset 0, plain store
    }
}

// ---------------- 64->64 conv, 3x3, stride 2, pad 1, smem tiled, ic-split --------
// Input is the RAW previous accumulator; previous layer's bias+BN+ReLU is applied
// during smem staging using the folded scale/shift tables.
// Block: 128 threads. 32 output channels x 8x8 output spatial tile per block.
// Thread micro-tile: 4 oc x (2x2) spatial -> 16 accumulators, 61 LDS / 144 FFMA per ic.
__global__ void conv64_kernel(const float* __restrict__ convs_w, int layer, int ICS)
{
    const int HIN = 256 >> layer;
    const int HOUT = HIN >> 1;
    const int tilesx = HOUT >> 3;
    const int tile = blockIdx.x;
    const int ty = tile / tilesx, tx = tile % tilesx;
    const int oy0 = ty * 8, ox0 = tx * 8;
    const int ocb = blockIdx.y * 32;
    const int ic0 = blockIdx.z * ICS;

    const float* __restrict__ in  = g_accs + OFFS[layer - 1];
    float* __restrict__ out       = g_accs + OFFS[layer];
    const float* __restrict__ w   = convs_w + (layer - 1) * 36864;
    const float* __restrict__ scl = g_scale + (layer - 1) * 64;
    const float* __restrict__ shf = g_shift + (layer - 1) * 64;

    __shared__ float s_in[289];   // 17x17 input patch for one ic
    __shared__ float s_w[288];    // [k][32] weights for 32 oc, one ic

    const int tid = threadIdx.x;
    const int ocg = tid & 7;      // oc group: oc = ocb + ocg*4 + j
    const int sps = tid >> 3;     // 16 spatial slots -> 4x4 grid of 2x2 micros
    const int my = sps >> 2, mx = sps & 3;

    float acc[4][4];
    #pragma unroll
    for (int j = 0; j < 4; j++)
        #pragma unroll
        for (int p = 0; p < 4; p++) acc[j][p] = 0.0f;

    const int iy0 = oy0 * 2 - 1, ix0 = ox0 * 2 - 1;

    for (int icc = 0; icc < ICS; icc++) {
        const int ic = ic0 + icc;
        const float sc = scl[ic], sh = shf[ic];
        const float* __restrict__ inp = in + ic * HIN * HIN;
        __syncthreads();
        for (int idx = tid; idx < 289; idx += 128) {
            int r = idx / 17, c = idx - r * 17;
            int gy = iy0 + r, gx = ix0 + c;
            float vv = 0.0f;
            if ((unsigned)gy < (unsigned)HIN && (unsigned)gx < (unsigned)HIN)
                vv = fmaxf(fmaf(inp[gy * HIN + gx], sc, sh), 0.0f);  // bias+BN+ReLU fused
            s_in[idx] = vv;
        }
        for (int idx = tid; idx < 288; idx += 128) {
            int ocl = idx & 31, k = idx >> 5;
            s_w[idx] = w[(ocb + ocl) * 576 + ic * 9 + k];
        }
        __syncthreads();

        float win[5][5];
        #pragma unroll
        for (int r = 0; r < 5; r++)
            #pragma unroll
            for (int c = 0; c < 5; c++)
                win[r][c] = s_in[(4 * my + r) * 17 + 4 * mx + c];

        #pragma unroll
        for (int ky = 0; ky < 3; ky++)
            #pragma unroll
            for (int kx = 0; kx < 3; kx++) {
                const int k = ky * 3 + kx;
                float w0 = s_w[k * 32 + ocg * 4 + 0];
                float w1 = s_w[k * 32 + ocg * 4 + 1];
                float w2 = s_w[k * 32 + ocg * 4 + 2];
                float w3 = s_w[k * 32 + ocg * 4 + 3];
                #pragma unroll
                for (int py = 0; py < 2; py++)
                    #pragma unroll
                    for (int px = 0; px < 2; px++) {
                        float v = win[2 * py + ky][2 * px + kx];
                        int p = py * 2 + px;
                        acc[0][p] = fmaf(v, w0, acc[0][p]);
                        acc[1][p] = fmaf(v, w1, acc[1][p]);
                        acc[2][p] = fmaf(v, w2, acc[2][p]);
                        acc[3][p] = fmaf(v, w3, acc[3][p]);
                    }
            }
    }

    #pragma unroll
    for (int j = 0; j < 4; j++) {
        int oc = ocb + ocg * 4 + j;
        #pragma unroll
        for (int py = 0; py < 2; py++)
            #pragma unroll
            for (int px = 0; px < 2; px++) {
                int oy = oy0 + 2 * my + py, ox = ox0 + 2 * mx + px;
                atomicAdd(&out[(oc * HOUT + oy) * HOUT + ox], acc[j][py * 2 + px]);
            }
    }
}

// ---------------- head: BN4 + ReLU + global mean pool + GEMV + argmax ------------
__global__ void head_kernel(const float* __restrict__ head_w,
                            const float* __restrict__ head_b,
                            int* __restrict__ out)
{
    int c = threadIdx.x;  // 64 channels
    const float* a4 = g_accs + OFFS[4];
    float sc = g_scale[256 + c], sh = g_shift[256 + c];
    float s = 0.0f;
    #pragma unroll 8
    for (int p = 0; p < 64; p++) s += fmaxf(fmaf(a4[c * 64 + p], sc, sh), 0.0f);
    float feat = s * (1.0f / 64.0f);
    __shared__ float l0[64], l1[64];
    l0[c] = feat * head_w[c];
    l1[c] = feat * head_w[64 + c];
    __syncthreads();
    if (c == 0) {
        float A = head_b[0], B = head_b[1];
        for (int i = 0; i < 64; i++) { A += l0[i]; B += l1[i]; }
        out[0] = (B > A) ? 1 : 0;  // argmax, ties -> index 0 (matches jnp.argmax)
    }
}

// ---------------- launch ----------------
extern "C" void kernel_launch(void* const* d_in, const int* in_sizes, int n_in,
                              void* d_out, int out_size)
{
    const float* image   = (const float*)d_in[0];
    const float* conv0_w = (const float*)d_in[1];
    const float* conv0_b = (const float*)d_in[2];
    const float* convs_w = (const float*)d_in[3];
    const float* convs_b = (const float*)d_in[4];
    const float* bn_g    = (const float*)d_in[5];
    const float* bn_b    = (const float*)d_in[6];
    const float* bn_m    = (const float*)d_in[7];
    const float* bn_v    = (const float*)d_in[8];
    const float* head_w  = (const float*)d_in[9];
    const float* head_b  = (const float*)d_in[10];
    int* outp = (int*)d_out;

    prep_kernel<<<256, 256>>>(conv0_b, convs_b, bn_g, bn_b, bn_m, bn_v);
    col_scan_kernel<<<32, 256>>>(image);
    row_scan_kernel<<<1024, 256>>>(image);
    bounds_kernel<<<1, 256>>>();
    resize_kernel<<<256, 256>>>(image);
    dilate_kernel<<<256, 256>>>();
    conv0_kernel<<<dim3(64, 16), 256>>>(conv0_w);
    conv64_kernel<<<dim3(64, 2,  2), 128>>>(convs_w, 1, 32);  // 128x128 -> 64x64
    conv64_kernel<<<dim3(16, 2,  4), 128>>>(convs_w, 2, 16);  // 64x64   -> 32x32
    conv64_kernel<<<dim3( 4, 2,  8), 128>>>(convs_w, 3,  8);  // 32x32   -> 16x16
    conv64_kernel<<<dim3( 1, 2, 16), 128>>>(convs_w, 4,  4);  // 16x16   -> 8x8
    head_kernel<<<1, 64>>>(head_w, head_b, outp);
}

// round 2
// speedup vs baseline: 1.6162x; 1.6162x over previous
#include <cuda_runtime.h>
#include <math.h>

#define IMG_W 8192
typedef unsigned long long ull;

// ---------------- scratch (device globals; no allocation allowed) ----------------
// acc0 64x128x128, acc1 64x64x64, acc2 64x32x32, acc3 64x16x16, acc4 64x8x8
__device__ float g_accs[1396736];
__device__ const int OFFS[5] = {0, 1048576, 1310720, 1376256, 1392640};
__device__ int   g_bounds[4];   // top(min), bottom(max), left(min), right(max)
__device__ float g_scale[320];  // folded BN scale  (5 layers x 64 ch)
__device__ float g_shift[320];  // folded BN shift (incl. conv bias)

// packed f32x2 helpers (sm_103a): 2 MACs per instruction
#define PACK2(dst, v)  asm("mov.b64 %0, {%1, %1};" : "=l"(dst) : "r"(__float_as_uint(v)))
#define FMA2(acc, a, b) asm("fma.rn.f32x2 %0, %1, %2, %0;" : "+l"(acc) : "l"(a), "l"(b))
#define UNPACK2(lo, hi, v) asm("mov.b64 {%0, %1}, %2;" : "=r"(lo), "=r"(hi) : "l"(v))

// ---------------- prep: zero atomic accumulators + fold BN + bounds sentinels ----
__global__ void prep_kernel(const float* __restrict__ conv0_b,
                            const float* __restrict__ convs_b,
                            const float* __restrict__ gamma,
                            const float* __restrict__ beta,
                            const float* __restrict__ mean,
                            const float* __restrict__ var)
{
    int gid = blockIdx.x * blockDim.x + threadIdx.x;
    int stride = gridDim.x * blockDim.x;
    for (int k = gid; k < 348160; k += stride) g_accs[1048576 + k] = 0.0f;
    if (gid == 0) {
        g_bounds[0] = 1 << 30; g_bounds[1] = -1;
        g_bounds[2] = 1 << 30; g_bounds[3] = -1;
    }
    if (gid < 320) {
        int l = gid >> 6, c = gid & 63;
        float sc = gamma[gid] / sqrtf(var[gid] + 1e-5f);
        float b = (l == 0) ? conv0_b[c] : convs_b[(l - 1) * 64 + c];
        g_scale[gid] = sc;
        g_shift[gid] = (b - mean[gid]) * sc + beta[gid];
    }
}

// ---------------- combined row+col variance scan with early exit -----------------
// blocks [0,32): columns (one col per thread). blocks [32,1056): rows (one per warp).
__global__ void scan_kernel(const float* __restrict__ img)
{
    __shared__ int smn[256], smx[256];
    const int b = blockIdx.x, tid = threadIdx.x;
    int mn = 1 << 30, mx = -1;
    int lo_idx, hi_idx;

    if (b < 32) {                     // column scan: col_var[c] = any(img[r][c]!=img[0][c])
        lo_idx = 2; hi_idx = 3;
        int c = b * 256 + tid;
        float ref = img[c];
        bool found = false;
        for (int r = 1; r < IMG_W; r++) {
            found |= (img[(size_t)r * IMG_W + c] != ref);
            if (__all_sync(0xffffffffu, found)) break;
        }
        if (found) { mn = c; mx = c; }
    } else {                          // row scan: row_var[r] = any(img[r][c]!=img[r][0])
        lo_idx = 0; hi_idx = 1;
        int row = (b - 32) * 8 + (tid >> 5);
        int lane = tid & 31;
        const float* rowp = img + (size_t)row * IMG_W;
        float v = rowp[lane];
        float ref = __shfl_sync(0xffffffffu, v, 0);
        int flag = __any_sync(0xffffffffu, v != ref) ? 1 : 0;
        for (int base = 32; base < IMG_W && !flag; base += 32)
            flag = __any_sync(0xffffffffu, rowp[base + lane] != ref) ? 1 : 0;
        if (lane == 0 && flag) { mn = row; mx = row; }
    }

    smn[tid] = mn; smx[tid] = mx;
    __syncthreads();
    for (int s = 128; s > 0; s >>= 1) {
        if (tid < s) { smn[tid] = min(smn[tid], smn[tid + s]); smx[tid] = max(smx[tid], smx[tid + s]); }
        __syncthreads();
    }
    if (tid == 0 && smx[0] >= 0) {
        atomicMin(&g_bounds[lo_idx], smn[0]);
        atomicMax(&g_bounds[hi_idx], smx[0]);
    }
}

// ---------------- fused crop/resize + dilate + conv0 -----------------------------
// 64 blocks, each computes a 16x16 spatial tile of conv0's 64x128x128 output.
__global__ void front_kernel(const float* __restrict__ img, const float* __restrict__ w0)
{
    __shared__ float s_res[37 * 37];  // 255 - resized, patch with halo
    __shared__ float s_dil[33 * 33];  // conv0 input patch (255 - clip(dilate))
    __shared__ float s_w[576];
    const int b = blockIdx.x, tid = threadIdx.x;
    const int ty = b >> 3, tx = b & 7;
    const int oy0 = ty * 16, ox0 = tx * 16;

    int top = g_bounds[0], bottom = g_bounds[1], left = g_bounds[2], right = g_bounds[3];
    if (bottom < 0) { top = 0; bottom = IMG_W - 1; }
    if (right  < 0) { left = 0; right  = IMG_W - 1; }

    for (int i = tid; i < 576; i += 256) s_w[i] = w0[i];

    const int ry0 = 2 * oy0 - 3, rx0 = 2 * ox0 - 3;
    const float szy = (float)(bottom - top + 1);
    const float szx = (float)(right - left + 1);
    for (int i = tid; i < 37 * 37; i += 256) {
        int r = i / 37, c = i - r * 37;
        int gy = ry0 + r, gx = rx0 + c;
        float val = 0.0f;
        if ((unsigned)gy < 256u && (unsigned)gx < 256u) {
            float cy = (float)top  + ((float)gy + 0.5f) * szy * (1.0f / 256.0f) - 0.5f;
            float cx = (float)left + ((float)gx + 0.5f) * szx * (1.0f / 256.0f) - 0.5f;
            float fy0 = floorf(cy), fx0 = floorf(cx);
            float wy = cy - fy0, wx = cx - fx0;
            int y0 = (int)fminf(fmaxf(fy0,        (float)top),  (float)bottom);
            int y1 = (int)fminf(fmaxf(fy0 + 1.0f, (float)top),  (float)bottom);
            int x0 = (int)fminf(fmaxf(fx0,        (float)left), (float)right);
            int x1 = (int)fminf(fmaxf(fx0 + 1.0f, (float)left), (float)right);
            float v00 = img[(size_t)y0 * IMG_W + x0];
            float v01 = img[(size_t)y0 * IMG_W + x1];
            float v10 = img[(size_t)y1 * IMG_W + x0];
            float v11 = img[(size_t)y1 * IMG_W + x1];
            float tr = v00 * (1.0f - wx) + v01 * wx;
            float br = v10 * (1.0f - wx) + v11 * wx;
            val = 255.0f - (tr * (1.0f - wy) + br * wy);
        }
        s_res[i] = val;   // invalid -> 0 == zero-pad contribution for 'SAME' dilate
    }
    __syncthreads();

    for (int i = tid; i < 33 * 33; i += 256) {
        int r = i / 33, c = i - r * 33;
        int gy = 2 * oy0 - 1 + r, gx = 2 * ox0 - 1 + c;
        float val = 0.0f;  // conv0 zero padding for out-of-image coords
        if ((unsigned)gy < 256u && (unsigned)gx < 256u) {
            float s = 0.0f;
            #pragma unroll
            for (int dy = 0; dy <= 4; dy += 2)
                #pragma unroll
                for (int dx = 0; dx <= 4; dx += 2)
                    s += s_res[(r + dy) * 37 + (c + dx)];
            val = 255.0f - fminf(fmaxf(s, 0.0f), 255.0f);
        }
        s_dil[i] = val;
    }
    __syncthreads();

    const int ly = tid >> 4, lx = tid & 15;
    float v[9];
    #pragma unroll
    for (int ky = 0; ky < 3; ky++)
        #pragma unroll
        for (int kx = 0; kx < 3; kx++)
            v[ky * 3 + kx] = s_dil[(2 * ly + ky) * 33 + (2 * lx + kx)];

    const int oy = oy0 + ly, ox = ox0 + lx;
    #pragma unroll 4
    for (int oc = 0; oc < 64; oc++) {
        float a = 0.0f;
        #pragma unroll
        for (int k = 0; k < 9; k++) a = fmaf(v[k], s_w[oc * 9 + k], a);
        g_accs[(oc * 128 + oy) * 128 + ox] = a;   // acc0, raw conv output
    }
}

// ---------------- 64->64 conv, 3x3, stride 2, pad 1; f32x2 microkernel -----------
// Block: 256 threads = 64 oc x 8x8 spatial tile. Thread: 4 oc x 2x2 spatial.
// Weights for the block's ic-slice preloaded once; input staged 4 ics per barrier.
// Previous layer's bias+BN+ReLU applied during staging (folded tables).
__global__ void conv64_kernel(const float* __restrict__ convs_w, int layer, int ICS)
{
    const int HIN = 256 >> layer;
    const int HOUT = HIN >> 1;
    const int tilesx = HOUT >> 3;
    const int tile = blockIdx.x;
    const int ty = tile / tilesx, tx = tile - ty * tilesx;
    const int oy0 = ty * 8, ox0 = tx * 8;
    const int ic0 = blockIdx.y * ICS;

    const float* __restrict__ in  = g_accs + OFFS[layer - 1];
    float* __restrict__ out       = g_accs + OFFS[layer];
    const float* __restrict__ w   = convs_w + (layer - 1) * 36864;
    const float* __restrict__ scl = g_scale + (layer - 1) * 64;
    const float* __restrict__ shf = g_shift + (layer - 1) * 64;

    __shared__ float s_w[9216];        // [icc][k][64] for up to 16 ics
    __shared__ float s_in[4 * 289];    // 4 x (17x17) input patches

    const int tid = threadIdx.x;
    const int ocg = tid & 15;          // 16 oc groups of 4
    const int sps = tid >> 4;          // 16 spatial slots (4x4 grid of 2x2 micros)
    const int my = sps >> 2, mx = sps & 3;

    // preload all weights for this ic slice: smem layout [(icc*9+k)*64 + oc]
    const int nw = ICS * 576;
    const int icsn = ICS * 9;
    for (int idx = tid; idx < nw; idx += 256) {
        int oc = idx / icsn;
        int rem = idx - oc * icsn;
        int icc = rem / 9, k = rem - icc * 9;
        s_w[(icc * 9 + k) * 64 + oc] = w[oc * 576 + (ic0 + icc) * 9 + k];
    }

    ull acc[2][4];                     // [oc pair][spatial px], packed f32x2
    #pragma unroll
    for (int j = 0; j < 2; j++)
        #pragma unroll
        for (int p = 0; p < 4; p++) acc[j][p] = 0ull;

    const int iy0 = oy0 * 2 - 1, ix0 = ox0 * 2 - 1;

    for (int cc = 0; cc < ICS; cc += 4) {
        const int nch = min(4, ICS - cc);
        __syncthreads();
        for (int idx = tid; idx < nch * 289; idx += 256) {
            int ch = idx / 289, pos = idx - ch * 289;
            int r = pos / 17, c = pos - r * 17;
            int ic = ic0 + cc + ch;
            int gy = iy0 + r, gx = ix0 + c;
            float vv = 0.0f;
            if ((unsigned)gy < (unsigned)HIN && (unsigned)gx < (unsigned)HIN)
                vv = fmaxf(fmaf(in[ic * HIN * HIN + gy * HIN + gx], scl[ic], shf[ic]), 0.0f);
            s_in[ch * 289 + pos] = vv;
        }
        __syncthreads();

        for (int ch = 0; ch < nch; ch++) {
            const int icc = cc + ch;
            float win[5][5];
            #pragma unroll
            for (int r = 0; r < 5; r++)
                #pragma unroll
                for (int c = 0; c < 5; c++)
                    win[r][c] = s_in[ch * 289 + (4 * my + r) * 17 + 4 * mx + c];

            #pragma unroll
            for (int ky = 0; ky < 3; ky++)
                #pragma unroll
                for (int kx = 0; kx < 3; kx++) {
                    const int k = ky * 3 + kx;
                    ulonglong2 wv = reinterpret_cast<const ulonglong2*>(s_w)[(icc * 9 + k) * 16 + ocg];
                    #pragma unroll
                    for (int py = 0; py < 2; py++)
                        #pragma unroll
                        for (int px = 0; px < 2; px++) {
                            ull v2;
                            PACK2(v2, win[2 * py + ky][2 * px + kx]);
                            const int p = py * 2 + px;
                            FMA2(acc[0][p], v2, wv.x);   // oc ocg*4+0, +1
                            FMA2(acc[1][p], v2, wv.y);   // oc ocg*4+2, +3
                        }
                }
        }
    }

    #pragma unroll
    for (int j = 0; j < 2; j++)
        #pragma unroll
        for (int py = 0; py < 2; py++)
            #pragma unroll
            for (int px = 0; px < 2; px++) {
                unsigned lo, hi;
                UNPACK2(lo, hi, acc[j][py * 2 + px]);
                int oy = oy0 + 2 * my + py, ox = ox0 + 2 * mx + px;
                int oc = ocg * 4 + j * 2;
                atomicAdd(&out[(oc * HOUT + oy) * HOUT + ox], __uint_as_float(lo));
                atomicAdd(&out[((oc + 1) * HOUT + oy) * HOUT + ox], __uint_as_float(hi));
            }
}

// ---------------- head: BN4 + ReLU + global mean pool + GEMV + argmax ------------
__global__ void head_kernel(const float* __restrict__ head_w,
                            const float* __restrict__ head_b,
                            int* __restrict__ out)
{
    int c = threadIdx.x;  // 64 channels
    const float* a4 = g_accs + OFFS[4];
    float sc = g_scale[256 + c], sh = g_shift[256 + c];
    float s = 0.0f;
    #pragma unroll 8
    for (int p = 0; p < 64; p++) s += fmaxf(fmaf(a4[c * 64 + p], sc, sh), 0.0f);
    float feat = s * (1.0f / 64.0f);
    __shared__ float l0[64], l1[64];
    l0[c] = feat * head_w[c];
    l1[c] = feat * head_w[64 + c];
    __syncthreads();
    if (c == 0) {
        float A = head_b[0], B = head_b[1];
        for (int i = 0; i < 64; i++) { A += l0[i]; B += l1[i]; }
        out[0] = (B > A) ? 1 : 0;
    }
}

// ---------------- launch (8 graph nodes) ----------------
extern "C" void kernel_launch(void* const* d_in, const int* in_sizes, int n_in,
                              void* d_out, int out_size)
{
    const float* image   = (const float*)d_in[0];
    const float* conv0_w = (const float*)d_in[1];
    const float* conv0_b = (const float*)d_in[2];
    const float* convs_w = (const float*)d_in[3];
    const float* convs_b = (const float*)d_in[4];
    const float* bn_g    = (const float*)d_in[5];
    const float* bn_b    = (const float*)d_in[6];
    const float* bn_m    = (const float*)d_in[7];
    const float* bn_v    = (const float*)d_in[8];
    const float* head_w  = (const float*)d_in[9];
    const float* head_b  = (const float*)d_in[10];
    int* outp = (int*)d_out;

    prep_kernel<<<256, 256>>>(conv0_b, convs_b, bn_g, bn_b, bn_m, bn_v);
    scan_kernel<<<1056, 256>>>(image);
    front_kernel<<<64, 256>>>(image, conv0_w);
    conv64_kernel<<<dim3(64,  4), 256>>>(convs_w, 1, 16);  // 128->64
    conv64_kernel<<<dim3(16,  8), 256>>>(convs_w, 2,  8);  // 64->32
    conv64_kernel<<<dim3( 4, 16), 256>>>(convs_w, 3,  4);  // 32->16
    conv64_kernel<<<dim3( 1, 32), 256>>>(convs_w, 4,  2);  // 16->8
    head_kernel<<<1, 64>>>(head_w, head_b, outp);
}

// round 3
// speedup vs baseline: 1.8106x; 1.1203x over previous
#include <cuda_runtime.h>
#include <math.h>

#define IMG_W 8192
typedef unsigned long long ull;

// ---------------- scratch (device globals; no allocation allowed) ----------------
// acc0 64x128x128 @0, acc1 64x64x64 @1048576, acc2 64x32x32 @1310720,
// acc3 64x16x16 @1376256, acc4 64x8x8 @1392640
__device__ float g_accs[1396736];
__device__ int   g_bounds[4];   // top(min), bottom(max), left(min), right(max)
__device__ float g_scale[320];  // folded BN scale  (5 layers x 64 ch)
__device__ float g_shift[320];  // folded BN shift (incl. conv bias)

// packed f32x2 helpers (sm_103a): 2 MACs per instruction
#define PACK2(dst, v)  asm("mov.b64 %0, {%1, %1};" : "=l"(dst) : "r"(__float_as_uint(v)))
#define FMA2(acc, a, b) asm("fma.rn.f32x2 %0, %1, %2, %0;" : "+l"(acc) : "l"(a), "l"(b))
#define UNPACK2(lo, hi, v) asm("mov.b64 {%0, %1}, %2;" : "=r"(lo), "=r"(hi) : "l"(v))

template<int L> struct Offs;   // input offset for conv layer L, output = Offs<L+1>
template<> struct Offs<0> { static const int v = 0; };
template<> struct Offs<1> { static const int v = 1048576; };
template<> struct Offs<2> { static const int v = 1310720; };
template<> struct Offs<3> { static const int v = 1376256; };
template<> struct Offs<4> { static const int v = 1392640; };

// ---------------- prep: zero atomic accumulators + fold BN + bounds sentinels ----
__global__ void prep_kernel(const float* __restrict__ conv0_b,
                            const float* __restrict__ convs_b,
                            const float* __restrict__ gamma,
                            const float* __restrict__ beta,
                            const float* __restrict__ mean,
                            const float* __restrict__ var)
{
    int gid = blockIdx.x * blockDim.x + threadIdx.x;
    int stride = gridDim.x * blockDim.x;
    for (int k = gid; k < 348160; k += stride) g_accs[1048576 + k] = 0.0f;
    if (gid == 0) {
        g_bounds[0] = 1 << 30; g_bounds[1] = -1;
        g_bounds[2] = 1 << 30; g_bounds[3] = -1;
    }
    if (gid < 320) {
        int l = gid >> 6, c = gid & 63;
        float sc = gamma[gid] / sqrtf(var[gid] + 1e-5f);
        float b = (l == 0) ? conv0_b[c] : convs_b[(l - 1) * 64 + c];
        g_scale[gid] = sc;
        g_shift[gid] = (b - mean[gid]) * sc + beta[gid];
    }
}

// ---------------- combined row+col variance scan with early exit -----------------
__global__ void scan_kernel(const float* __restrict__ img)
{
    __shared__ int smn[256], smx[256];
    const int b = blockIdx.x, tid = threadIdx.x;
    int mn = 1 << 30, mx = -1;
    int lo_idx, hi_idx;

    if (b < 32) {                     // column scan
        lo_idx = 2; hi_idx = 3;
        int c = b * 256 + tid;
        float ref = img[c];
        bool found = false;
        for (int r = 1; r < IMG_W; r++) {
            found |= (img[(size_t)r * IMG_W + c] != ref);
            if (__all_sync(0xffffffffu, found)) break;
        }
        if (found) { mn = c; mx = c; }
    } else {                          // row scan (one warp per row)
        lo_idx = 0; hi_idx = 1;
        int row = (b - 32) * 8 + (tid >> 5);
        int lane = tid & 31;
        const float* rowp = img + (size_t)row * IMG_W;
        float v = rowp[lane];
        float ref = __shfl_sync(0xffffffffu, v, 0);
        int flag = __any_sync(0xffffffffu, v != ref) ? 1 : 0;
        for (int base = 32; base < IMG_W && !flag; base += 32)
            flag = __any_sync(0xffffffffu, rowp[base + lane] != ref) ? 1 : 0;
        if (lane == 0 && flag) { mn = row; mx = row; }
    }

    smn[tid] = mn; smx[tid] = mx;
    __syncthreads();
    for (int s = 128; s > 0; s >>= 1) {
        if (tid < s) { smn[tid] = min(smn[tid], smn[tid + s]); smx[tid] = max(smx[tid], smx[tid + s]); }
        __syncthreads();
    }
    if (tid == 0 && smx[0] >= 0) {
        atomicMin(&g_bounds[lo_idx], smn[0]);
        atomicMax(&g_bounds[hi_idx], smx[0]);
    }
}

// ---------------- fused crop/resize + dilate + conv0 -----------------------------
__global__ void front_kernel(const float* __restrict__ img, const float* __restrict__ w0)
{
    __shared__ float s_res[37 * 37];
    __shared__ float s_dil[33 * 33];
    __shared__ float s_w[576];
    const int b = blockIdx.x, tid = threadIdx.x;
    const int ty = b >> 3, tx = b & 7;
    const int oy0 = ty * 16, ox0 = tx * 16;

    int top = g_bounds[0], bottom = g_bounds[1], left = g_bounds[2], right = g_bounds[3];
    if (bottom < 0) { top = 0; bottom = IMG_W - 1; }
    if (right  < 0) { left = 0; right  = IMG_W - 1; }

    for (int i = tid; i < 576; i += 256) s_w[i] = w0[i];

    const int ry0 = 2 * oy0 - 3, rx0 = 2 * ox0 - 3;
    const float szy = (float)(bottom - top + 1);
    const float szx = (float)(right - left + 1);
    for (int i = tid; i < 37 * 37; i += 256) {
        int r = i / 37, c = i - r * 37;
        int gy = ry0 + r, gx = rx0 + c;
        float val = 0.0f;
        if ((unsigned)gy < 256u && (unsigned)gx < 256u) {
            float cy = (float)top  + ((float)gy + 0.5f) * szy * (1.0f / 256.0f) - 0.5f;
            float cx = (float)left + ((float)gx + 0.5f) * szx * (1.0f / 256.0f) - 0.5f;
            float fy0 = floorf(cy), fx0 = floorf(cx);
            float wy = cy - fy0, wx = cx - fx0;
            int y0 = (int)fminf(fmaxf(fy0,        (float)top),  (float)bottom);
            int y1 = (int)fminf(fmaxf(fy0 + 1.0f, (float)top),  (float)bottom);
            int x0 = (int)fminf(fmaxf(fx0,        (float)left), (float)right);
            int x1 = (int)fminf(fmaxf(fx0 + 1.0f, (float)left), (float)right);
            float v00 = img[(size_t)y0 * IMG_W + x0];
            float v01 = img[(size_t)y0 * IMG_W + x1];
            float v10 = img[(size_t)y1 * IMG_W + x0];
            float v11 = img[(size_t)y1 * IMG_W + x1];
            float tr = v00 * (1.0f - wx) + v01 * wx;
            float br = v10 * (1.0f - wx) + v11 * wx;
            val = 255.0f - (tr * (1.0f - wy) + br * wy);
        }
        s_res[i] = val;
    }
    __syncthreads();

    for (int i = tid; i < 33 * 33; i += 256) {
        int r = i / 33, c = i - r * 33;
        int gy = 2 * oy0 - 1 + r, gx = 2 * ox0 - 1 + c;
        float val = 0.0f;
        if ((unsigned)gy < 256u && (unsigned)gx < 256u) {
            float s = 0.0f;
            #pragma unroll
            for (int dy = 0; dy <= 4; dy += 2)
                #pragma unroll
                for (int dx = 0; dx <= 4; dx += 2)
                    s += s_res[(r + dy) * 37 + (c + dx)];
            val = 255.0f - fminf(fmaxf(s, 0.0f), 255.0f);
        }
        s_dil[i] = val;
    }
    __syncthreads();

    const int ly = tid >> 4, lx = tid & 15;
    float v[9];
    #pragma unroll
    for (int ky = 0; ky < 3; ky++)
        #pragma unroll
        for (int kx = 0; kx < 3; kx++)
            v[ky * 3 + kx] = s_dil[(2 * ly + ky) * 33 + (2 * lx + kx)];

    const int oy = oy0 + ly, ox = ox0 + lx;
    #pragma unroll 4
    for (int oc = 0; oc < 64; oc++) {
        float a = 0.0f;
        #pragma unroll
        for (int k = 0; k < 9; k++) a = fmaf(v[k], s_w[oc * 9 + k], a);
        g_accs[(oc * 128 + oy) * 128 + ox] = a;
    }
}

// ---------------- 64->64 conv, 3x3, stride 2, pad 1; single-stage smem -----------
// Block: 256 threads = 64 oc x 8x8 spatial tile. Thread: 4 oc x 2x2 spatial.
// All ICS input channels + weights staged ONCE -> one barrier per block.
// Input rows padded to 20 floats so window rows load as LDS.128 + LDS.32.
template<int LAYER, int ICS>
__global__ void __launch_bounds__(256) conv64_kernel(const float* __restrict__ convs_w)
{
    constexpr int HIN = 256 >> LAYER;
    constexpr int HOUT = HIN >> 1;
    constexpr int TILESX = HOUT >> 3;
    const int tile = blockIdx.x;
    const int ty = tile / TILESX, tx = tile - ty * TILESX;
    const int oy0 = ty * 8, ox0 = tx * 8;
    const int ic0 = blockIdx.y * ICS;

    const float* __restrict__ in  = g_accs + Offs<LAYER - 1>::v;
    float* __restrict__ out       = g_accs + Offs<LAYER>::v;
    const float* __restrict__ w   = convs_w + (LAYER - 1) * 36864;
    const float* __restrict__ scl = g_scale + (LAYER - 1) * 64;
    const float* __restrict__ shf = g_shift + (LAYER - 1) * 64;

    __shared__ __align__(16) float s_w[ICS * 576];   // [(icc*9+k)*64 + oc]
    __shared__ __align__(16) float s_in[ICS * 340];  // ICS x (17 rows x 20 cols padded)

    const int tid = threadIdx.x;

    // stage weights for this ic slice
    for (int idx = tid; idx < ICS * 576; idx += 256) {
        int oc = idx / (ICS * 9);
        int rem = idx - oc * (ICS * 9);
        int icc = rem / 9, k = rem - icc * 9;
        s_w[(icc * 9 + k) * 64 + oc] = w[oc * 576 + (ic0 + icc) * 9 + k];
    }

    // stage all ICS input channels (17x17 window) with fused bias+BN+ReLU
    const int iy0 = oy0 * 2 - 1, ix0 = ox0 * 2 - 1;
    for (int idx = tid; idx < ICS * 289; idx += 256) {
        int ch = idx / 289, pos = idx - ch * 289;
        int r = pos / 17, c = pos - r * 17;
        int ic = ic0 + ch;
        int gy = iy0 + r, gx = ix0 + c;
        float vv = 0.0f;
        if ((unsigned)gy < (unsigned)HIN && (unsigned)gx < (unsigned)HIN)
            vv = fmaxf(fmaf(in[ic * HIN * HIN + gy * HIN + gx], scl[ic], shf[ic]), 0.0f);
        s_in[ch * 340 + r * 20 + c] = vv;
    }
    __syncthreads();   // the only barrier

    const int ocg = tid & 15;          // 16 oc groups of 4
    const int sps = tid >> 4;          // 4x4 grid of 2x2 micro-tiles
    const int my = sps >> 2, mx = sps & 3;

    ull acc[2][4];
    #pragma unroll
    for (int j = 0; j < 2; j++)
        #pragma unroll
        for (int p = 0; p < 4; p++) acc[j][p] = 0ull;

    #pragma unroll
    for (int icc = 0; icc < ICS; icc++) {
        float win[5][5];
        const float* bp = s_in + icc * 340 + (4 * my) * 20 + 4 * mx;  // 16B-aligned
        #pragma unroll
        for (int r = 0; r < 5; r++) {
            float4 q = *reinterpret_cast<const float4*>(bp + r * 20);
            win[r][0] = q.x; win[r][1] = q.y; win[r][2] = q.z; win[r][3] = q.w;
            win[r][4] = bp[r * 20 + 4];
        }
        #pragma unroll
        for (int ky = 0; ky < 3; ky++)
            #pragma unroll
            for (int kx = 0; kx < 3; kx++) {
                const int k = ky * 3 + kx;
                ulonglong2 wv = reinterpret_cast<const ulonglong2*>(s_w)[(icc * 9 + k) * 16 + ocg];
                #pragma unroll
                for (int py = 0; py < 2; py++)
                    #pragma unroll
                    for (int px = 0; px < 2; px++) {
                        ull v2;
                        PACK2(v2, win[2 * py + ky][2 * px + kx]);
                        const int p = py * 2 + px;
                        FMA2(acc[0][p], v2, wv.x);
                        FMA2(acc[1][p], v2, wv.y);
                    }
            }
    }

    #pragma unroll
    for (int j = 0; j < 2; j++)
        #pragma unroll
        for (int py = 0; py < 2; py++)
            #pragma unroll
            for (int px = 0; px < 2; px++) {
                unsigned lo, hi;
                UNPACK2(lo, hi, acc[j][py * 2 + px]);
                int oy = oy0 + 2 * my + py, ox = ox0 + 2 * mx + px;
                int oc = ocg * 4 + j * 2;
                atomicAdd(&out[(oc * HOUT + oy) * HOUT + ox], __uint_as_float(lo));
                atomicAdd(&out[((oc + 1) * HOUT + oy) * HOUT + ox], __uint_as_float(hi));
            }
}

// ---------------- head: BN4 + ReLU + global mean pool + GEMV + argmax ------------
__global__ void head_kernel(const float* __restrict__ head_w,
                            const float* __restrict__ head_b,
                            int* __restrict__ out)
{
    int c = threadIdx.x;  // 64 channels
    const float* a4 = g_accs + 1392640;
    float sc = g_scale[256 + c], sh = g_shift[256 + c];
    float s = 0.0f;
    #pragma unroll 8
    for (int p = 0; p < 64; p++) s += fmaxf(fmaf(a4[c * 64 + p], sc, sh), 0.0f);
    float feat = s * (1.0f / 64.0f);
    __shared__ float l0[64], l1[64];
    l0[c] = feat * head_w[c];
    l1[c] = feat * head_w[64 + c];
    __syncthreads();
    if (c == 0) {
        float A = head_b[0], B = head_b[1];
        for (int i = 0; i < 64; i++) { A += l0[i]; B += l1[i]; }
        out[0] = (B > A) ? 1 : 0;
    }
}

// ---------------- launch (8 graph nodes) ----------------
extern "C" void kernel_launch(void* const* d_in, const int* in_sizes, int n_in,
                              void* d_out, int out_size)
{
    const float* image   = (const float*)d_in[0];
    const float* conv0_w = (const float*)d_in[1];
    const float* conv0_b = (const float*)d_in[2];
    const float* convs_w = (const float*)d_in[3];
    const float* convs_b = (const float*)d_in[4];
    const float* bn_g    = (const float*)d_in[5];
    const float* bn_b    = (const float*)d_in[6];
    const float* bn_m    = (const float*)d_in[7];
    const float* bn_v    = (const float*)d_in[8];
    const float* head_w  = (const float*)d_in[9];
    const float* head_b  = (const float*)d_in[10];
    int* outp = (int*)d_out;

    prep_kernel<<<256, 256>>>(conv0_b, convs_b, bn_g, bn_b, bn_m, bn_v);
    scan_kernel<<<1056, 256>>>(image);
    front_kernel<<<64, 256>>>(image, conv0_w);
    conv64_kernel<1, 8><<<dim3(64,  8), 256>>>(convs_w);  // 128->64, 512 blocks
    conv64_kernel<2, 8><<<dim3(16,  8), 256>>>(convs_w);  // 64->32,  128 blocks
    conv64_kernel<3, 4><<<dim3( 4, 16), 256>>>(convs_w);  // 32->16,   64 blocks
    conv64_kernel<4, 2><<<dim3( 1, 32), 256>>>(convs_w);  // 16->8,    32 blocks
    head_kernel<<<1, 64>>>(head_w, head_b, outp);
}